// round 8
// baseline (speedup 1.0000x reference)
#include <cuda_runtime.h>
#include <cuda_bf16.h>

// Problem constants: N=2,000,000 rows, P=64 features, C=100 classes.
#define PFEAT      64
#define NCLASS     100
#define NWARPS     16         // warps per CTA; class ownership = cls & 15
#define THREADS1   (NWARPS * 32)
#define GRID1      592        // 148 SMs * 4 resident CTAs
#define BINS       (NCLASS * 32)      // [class][lane] bins

// Deterministic scratch (fixed-order reduction; no float atomics anywhere).
__device__ float2 g_s  [(size_t)GRID1 * BINS];   // ~15.2 MB  per-CTA per-(class,featpair) sums
__device__ float  g_ss [(size_t)GRID1 * BINS];   // ~7.6 MB   per-CTA per-(class,lane) ss partials
__device__ float  g_cnt[GRID1 * NCLASS];
__device__ double g_class[NCLASS];

// ---------------------------------------------------------------------------
// Kernel 1: warp w owns classes with (cls & 15) == w -> no atomics.
// One row per warp-op (full 32 lanes, float2 = features 2*lane, 2*lane+1):
// each lane only ever RMWs bin column [*, lane] -> no aliasing possible.
// ss is a per-(class,lane) scalar (per-feature ss eliminated algebraically);
// counts live in registers (lane c>>4 counts class c).
// ---------------------------------------------------------------------------
__global__ __launch_bounds__(THREADS1, 4)
void k1_accumulate(const float2* __restrict__ x2,
                   const int* __restrict__ t, int N)   // t is int32
{
    __shared__ float2 s_acc [BINS];   // 25.6 KB
    __shared__ float  ss_acc[BINS];   // 12.8 KB

    const int tid  = threadIdx.x;
    const int w    = tid >> 5;
    const int lane = tid & 31;

    for (int i = tid; i < BINS; i += THREADS1) {
        s_acc[i]  = make_float2(0.f, 0.f);
        ss_acc[i] = 0.f;
    }
    __syncthreads();

    const int chunk = (N + GRID1 - 1) / GRID1;
    const int beg   = blockIdx.x * chunk;
    const int end   = min(N, beg + chunk);

    float rc = 0.f;   // register count: lane k counts class w + 16*k

    for (int base = beg; base < end; base += 32) {
        int r   = base + lane;
        int cls = (r < end) ? t[r] : -1;
        bool own = (cls >= 0) && (cls < NCLASS) && ((cls & (NWARPS - 1)) == w);
        unsigned m = __ballot_sync(0xffffffffu, own);

        while (m) {
            // Extract up to 2 owned rows, THEN issue both 256B loads (MLP=2).
            int b0 = __ffs(m) - 1;  m &= m - 1;
            int b1 = -1;
            if (m) { b1 = __ffs(m) - 1; m &= m - 1; }

            int c0 = __shfl_sync(0xffffffffu, cls, b0);
            int c1 = __shfl_sync(0xffffffffu, cls, b1 & 31);

            float2 v0, v1;
            v0 = x2[(size_t)(base + b0) * (PFEAT / 2) + lane];
            if (b1 >= 0) v1 = x2[(size_t)(base + b1) * (PFEAT / 2) + lane];

            {   // row b0 (always valid)
                int idx = c0 * 32 + lane;
                float2 a = s_acc[idx];
                a.x += v0.x; a.y += v0.y;
                s_acc[idx] = a;
                ss_acc[idx] += v0.x * v0.x + v0.y * v0.y;
                if (lane == (c0 >> 4)) rc += 1.f;
            }
            if (b1 >= 0) {
                int idx = c1 * 32 + lane;
                float2 a = s_acc[idx];
                a.x += v1.x; a.y += v1.y;
                s_acc[idx] = a;
                ss_acc[idx] += v1.x * v1.x + v1.y * v1.y;
                if (lane == (c1 >> 4)) rc += 1.f;
            }
        }
    }
    __syncthreads();

    const size_t off = (size_t)blockIdx.x * BINS;
    for (int i = tid; i < BINS; i += THREADS1) {
        g_s [off + i] = s_acc[i];
        g_ss[off + i] = ss_acc[i];
    }
    // counts: warp w wrote class w + 16*lane into rc (lane < 7)
    int c = w + 16 * lane;
    if (lane < 7 && c < NCLASS)
        g_cnt[blockIdx.x * NCLASS + c] = rc;
}

// ---------------------------------------------------------------------------
// Kernel 2: one CTA (256 thr) per class; fixed-order reduction of partials.
// ---------------------------------------------------------------------------
__global__ __launch_bounds__(256)
void k2_per_class()
{
    const int c    = blockIdx.x;
    const int tid  = threadIdx.x;
    const int w    = tid >> 5;
    const int lane = tid & 31;

    __shared__ float2 sa[256];
    __shared__ float  sb[256];
    __shared__ float  sc[256];

    float2 a   = make_float2(0.f, 0.f);
    float  ssp = 0.f;
    for (int b = w; b < GRID1; b += 8) {           // coalesced 256B + 128B per (b,warp)
        size_t base = (size_t)b * BINS + c * 32 + lane;
        float2 p = g_s[base];
        a.x += p.x; a.y += p.y;
        ssp += g_ss[base];
    }
    sa[tid] = a;
    sb[tid] = ssp;

    float cn = 0.f;
    for (int b = tid; b < GRID1; b += 256) cn += g_cnt[b * NCLASS + c];
    sc[tid] = cn;
    __syncthreads();

    if (tid < 32) {
        float2 tot = sa[lane];
        float  ss  = sb[lane];
        float  n   = sc[lane];
        #pragma unroll
        for (int j = 1; j < 8; j++) {
            float2 p = sa[j * 32 + lane];
            tot.x += p.x; tot.y += p.y;
            ss += sb[j * 32 + lane];
            n  += sc[j * 32 + lane];
        }
        #pragma unroll
        for (int o = 16; o > 0; o >>= 1) n += __shfl_xor_sync(0xffffffffu, n, o);

        // dA = sum over features of s^2 ; dB = total SS for the class
        double dA = (double)tot.x * tot.x + (double)tot.y * tot.y;
        double dB = (double)ss;
        #pragma unroll
        for (int o = 16; o > 0; o >>= 1) {
            dA += __shfl_xor_sync(0xffffffffu, dA, o);
            dB += __shfl_xor_sync(0xffffffffu, dB, o);
        }

        double dn = (double)n;
        double contrib = (dB - dA / dn) / (dn - 1.0);
        if (lane == 0) g_class[c] = contrib;
    }
}

// ---------------------------------------------------------------------------
// Kernel 3: final deterministic reduction of the 100 class scalars.
// ---------------------------------------------------------------------------
__global__ void k3_final(float* __restrict__ out)
{
    if (threadIdx.x == 0) {
        double total = 0.0;
        for (int c = 0; c < NCLASS; c++) total += g_class[c];
        out[0] = (float)(total / (double)NCLASS);
    }
}

extern "C" void kernel_launch(void* const* d_in, const int* in_sizes, int n_in,
                              void* d_out, int out_size)
{
    const float2* x2  = (const float2*)d_in[0];
    const int*    t   = (const int*)d_in[1];          // int32 labels
    float*        out = (float*)d_out;
    const int N = in_sizes[0] / PFEAT;

    k1_accumulate<<<GRID1, THREADS1>>>(x2, t, N);
    k2_per_class<<<NCLASS, 256>>>();
    k3_final<<<1, 32>>>(out);
}